// round 16
// baseline (speedup 1.0000x reference)
#include <cuda_runtime.h>
#include <cuda_fp16.h>
#include <cstdint>

#define NN 25000
#define NE 400000
#define NG 64
#define F0 128
#define F1 512
#define SCAN_N 28672   // 1024 threads * 28 elems — scan coverage; arrays padded to this

// ================= device scratch (no allocs allowed) =================
__device__ __half g_x16[NN * F0];          // x in fp16
__device__ __half g_a1[NN * F0];           // agg1 fp16
__device__ __half g_h116[NN * F1];         // h1 fp16 (GEMM2 A + agg512 src)
__device__ __half g_a2[NN * F1];           // agg2 fp16
__device__ __half g_h216[NN * F1];         // h2 fp16 (pool src)
__device__ __half g_w1rh[F1 * F0], g_w1rl[F1 * F0];  // W1_rel^T  hi/lo
__device__ __half g_w1th[F1 * F0], g_w1tl[F1 * F0];  // W1_root^T hi/lo
__device__ __half g_w2rh[F1 * F1], g_w2rl[F1 * F1];  // W2_rel^T  hi/lo
__device__ __half g_w2th[F1 * F1], g_w2tl[F1 * F1];  // W2_root^T hi/lo
__device__ int   g_deg[SCAN_N];            // padded to scan coverage
__device__ int   g_rowptr[SCAN_N + 1];
__device__ int   g_epos[NE];               // per-edge slot within its dst row
__device__ int   g_srcs[NE];
__device__ float g_wgts[NE];
__device__ float g_gv[NG * F1];

// ================= helpers =================
__device__ __forceinline__ uint32_t smem_u32(const void* p) {
    uint32_t a;
    asm("{ .reg .u64 t; cvta.to.shared.u64 t, %1; cvt.u32.u64 %0, t; }" : "=r"(a) : "l"(p));
    return a;
}
__device__ __forceinline__ void ldm_x4(uint32_t* r, uint32_t addr) {
    asm volatile("ldmatrix.sync.aligned.m8n8.x4.shared.b16 {%0,%1,%2,%3}, [%4];"
                 : "=r"(r[0]), "=r"(r[1]), "=r"(r[2]), "=r"(r[3]) : "r"(addr));
}
__device__ __forceinline__ void mma_f16(float* c, const uint32_t* a, const uint32_t* b) {
    asm volatile("mma.sync.aligned.m16n8k16.row.col.f32.f16.f16.f32 "
                 "{%0,%1,%2,%3}, {%4,%5,%6,%7}, {%8,%9}, {%0,%1,%2,%3};"
                 : "+f"(c[0]), "+f"(c[1]), "+f"(c[2]), "+f"(c[3])
                 : "r"(a[0]), "r"(a[1]), "r"(a[2]), "r"(a[3]), "r"(b[0]), "r"(b[1]));
}
__device__ __forceinline__ void cpa16(uint32_t dst, const __half* src, uint32_t sz) {
    asm volatile("cp.async.cg.shared.global [%0], [%1], 16, %2;"
                 :: "r"(dst), "l"(__cvta_generic_to_global(src)), "r"(sz) : "memory");
}
__device__ __forceinline__ void cp_commit() {
    asm volatile("cp.async.commit_group;" ::: "memory");
}
template <int N>
__device__ __forceinline__ void cp_wait() {
    asm volatile("cp.async.wait_group %0;" :: "n"(N) : "memory");
}
__device__ __forceinline__ void split2h(float v, __half& h, __half& l) {
    h = __float2half_rn(v);
    l = __float2half_rn(v - __half2float(h));
}

// ================= CSR build =================
__global__ void k_zero() {
    int i = blockIdx.x * blockDim.x + threadIdx.x;
    if (i < SCAN_N) g_deg[i] = 0;
}
__global__ void k_hist(const int* __restrict__ ei) {
    int e = blockIdx.x * blockDim.x + threadIdx.x;
    if (e < NE) g_epos[e] = atomicAdd(&g_deg[ei[NE + e]], 1);
}
// vectorized single-block scan: 1024 thr x 28 elems (7 x int4), shuffle-based
#define SCH 28
__global__ __launch_bounds__(1024) void k_scan() {
    __shared__ int wsum[32];
    int t = threadIdx.x;
    int base = t * SCH;
    int v[SCH];
    int4* dv = reinterpret_cast<int4*>(v);
#pragma unroll
    for (int i = 0; i < SCH / 4; i++)
        dv[i] = *reinterpret_cast<const int4*>(&g_deg[base + i * 4]);
    int sum = 0;
#pragma unroll
    for (int i = 0; i < SCH; i++) { int x = v[i]; v[i] = sum; sum += x; }
    int lane = t & 31, wid = t >> 5;
    int inc = sum;
#pragma unroll
    for (int off = 1; off < 32; off <<= 1) {
        int y = __shfl_up_sync(0xFFFFFFFFu, inc, off);
        if (lane >= off) inc += y;
    }
    if (lane == 31) wsum[wid] = inc;
    __syncthreads();
    if (wid == 0) {
        int w = wsum[lane];
#pragma unroll
        for (int off = 1; off < 32; off <<= 1) {
            int y = __shfl_up_sync(0xFFFFFFFFu, w, off);
            if (lane >= off) w += y;
        }
        wsum[lane] = w;
    }
    __syncthreads();
    int warp_excl = (wid == 0) ? 0 : wsum[wid - 1];
    int thread_excl = warp_excl + (inc - sum);
#pragma unroll
    for (int i = 0; i < SCH; i++) v[i] += thread_excl;
#pragma unroll
    for (int i = 0; i < SCH / 4; i++)
        *reinterpret_cast<int4*>(&g_rowptr[base + i * 4]) = dv[i];
    if (t == 1023) g_rowptr[SCAN_N] = wsum[31];
}
// atomic-free scatter using hist-recorded slots
__global__ void k_scatter(const int* __restrict__ ei, const float* __restrict__ ea) {
    int e = blockIdx.x * blockDim.x + threadIdx.x;
    if (e >= NE) return;
    int pos = g_rowptr[ei[NE + e]] + g_epos[e];
    g_srcs[pos] = ei[e];
    g_wgts[pos] = ea[e];
}

// ================= prep: weight splits + x->fp16 (side stream) =================
#define W1_ELEMS (F0 * F1)   // 65536
#define W2_ELEMS (F1 * F1)   // 262144
#define PREP_W (2 * W1_ELEMS + 2 * W2_ELEMS)           // 655360
#define PREP_TOT (PREP_W + NN * F0)                    // + 3200000
__global__ void k_prepwx(const float* __restrict__ W1_rel, const float* __restrict__ W1_root,
                         const float* __restrict__ W2_rel, const float* __restrict__ W2_root,
                         const float* __restrict__ x) {
    int i = blockIdx.x * blockDim.x + threadIdx.x;
    if (i < PREP_W) {
        const float* W; __half* th; __half* tl; int K, idx;
        if (i < W1_ELEMS) { W = W1_rel; th = g_w1rh; tl = g_w1rl; K = F0; idx = i; }
        else if (i < 2 * W1_ELEMS) { W = W1_root; th = g_w1th; tl = g_w1tl; K = F0; idx = i - W1_ELEMS; }
        else if (i < 2 * W1_ELEMS + W2_ELEMS) { W = W2_rel; th = g_w2rh; tl = g_w2rl; K = F1; idx = i - 2 * W1_ELEMS; }
        else { W = W2_root; th = g_w2th; tl = g_w2tl; K = F1; idx = i - 2 * W1_ELEMS - W2_ELEMS; }
        int k = idx / F1, n = idx % F1;   // all weights are [K, 512]
        split2h(W[idx], th[n * K + k], tl[n * K + k]);
    } else if (i < PREP_TOT) {
        int n = i - PREP_W;
        g_x16[n] = __float2half_rn(x[n]);
    }
}

// ================= aggregation (gather-side, atomic-free) =================
__global__ void k_agg128() {
    int node = blockIdx.x * 4 + (threadIdx.x >> 5);
    if (node >= NN) return;
    int lane = threadIdx.x & 31;
    int beg = g_rowptr[node], end = g_rowptr[node + 1];
    float acc0 = 0.f, acc1 = 0.f, acc2 = 0.f, acc3 = 0.f;
    for (int p = beg; p < end; p++) {
        int s = g_srcs[p]; float w = g_wgts[p];
        uint2 raw = *reinterpret_cast<const uint2*>(&g_x16[s * F0 + lane * 4]);
        __half2 v01 = *reinterpret_cast<__half2*>(&raw.x);
        __half2 v23 = *reinterpret_cast<__half2*>(&raw.y);
        float2 f01 = __half22float2(v01), f23 = __half22float2(v23);
        acc0 += w * f01.x; acc1 += w * f01.y; acc2 += w * f23.x; acc3 += w * f23.y;
    }
    int o = node * F0 + lane * 4;
    __half2* dst = reinterpret_cast<__half2*>(&g_a1[o]);
    dst[0] = __floats2half2_rn(acc0, acc1);
    dst[1] = __floats2half2_rn(acc2, acc3);
}
__global__ void k_agg512() {
    int node = blockIdx.x, f4 = threadIdx.x;  // 128 threads, 4 halves each
    int beg = g_rowptr[node], end = g_rowptr[node + 1];
    float acc0 = 0.f, acc1 = 0.f, acc2 = 0.f, acc3 = 0.f;
    for (int p = beg; p < end; p++) {
        int s = g_srcs[p]; float w = g_wgts[p];
        uint2 raw = *reinterpret_cast<const uint2*>(&g_h116[(size_t)s * F1 + f4 * 4]);
        __half2 v01 = *reinterpret_cast<__half2*>(&raw.x);
        __half2 v23 = *reinterpret_cast<__half2*>(&raw.y);
        float2 f01 = __half22float2(v01), f23 = __half22float2(v23);
        acc0 += w * f01.x; acc1 += w * f01.y; acc2 += w * f23.x; acc3 += w * f23.y;
    }
    size_t o = (size_t)node * F1 + f4 * 4;
    __half2* dst = reinterpret_cast<__half2*>(&g_a2[o]);
    dst[0] = __floats2half2_rn(acc0, acc1);
    dst[1] = __floats2half2_rn(acc2, acc3);
}

// ================= persistent tensor-core dual GEMM (fp16 A + split-B, 2 passes) =================
#define CHK 64
#define PAD 72                       // fp16 row pitch (conflict-free ldmatrix)
#define ARR_BYTES (128 * PAD * 2)    // 18432
#define STG_BYTES (3 * ARR_BYTES)    // 55296 (A, Bh, Bl)
#define SMEM_BYTES (2 * STG_BYTES)   // 110592
#define GEMM_BLOCKS 296              // persistent: 2 CTAs/SM x 148 SMs

__global__ __launch_bounds__(256) void k_gemm_tc(
    const __half* __restrict__ A1, const __half* __restrict__ B1h, const __half* __restrict__ B1l,
    const __half* __restrict__ A2, const __half* __restrict__ B2h, const __half* __restrict__ B2l,
    int K, const float* __restrict__ bias,
    __half* __restrict__ C16,
    int M, int Nc) {
    extern __shared__ char smem[];
    uint32_t sb = smem_u32(smem);
    int tid = threadIdx.x;
    int wid = tid >> 5, lane = tid & 31;
    int warpM = wid >> 2, warpN = wid & 3;   // 2 x 4

    int ncpp = K / CHK;
    int NC = 2 * ncpp;
    int mtiles = (M + 127) / 128;
    int ntiles_n = Nc / 128;
    int ntiles = mtiles * ntiles_n;

    uint32_t a_lane = (uint32_t)((lane & 15) * PAD + (lane >> 4) * 8) * 2;
    uint32_t b_lane = (uint32_t)(((lane & 7) + ((lane >> 4) << 3)) * PAD
                                 + ((lane >> 3) & 1) * 8) * 2;

    for (int tile = blockIdx.x; tile < ntiles; tile += gridDim.x) {
        int m0 = (tile / ntiles_n) * 128;
        int n0 = (tile % ntiles_n) * 128;

        float acc[4][4][4];
#pragma unroll
        for (int i = 0; i < 4; i++)
#pragma unroll
            for (int j = 0; j < 4; j++)
#pragma unroll
                for (int q = 0; q < 4; q++) acc[i][j][q] = 0.f;

        // cp.async chunk c -> stage stg: arrays {A, Bh, Bl}
        auto issue = [&](int c, int stg) {
            int ph = c / ncpp;
            int kk = (c % ncpp) * CHK;
            const __half* arr0 = ph ? A2 : A1;
            const __half* arr1 = ph ? B2h : B1h;
            const __half* arr2 = ph ? B2l : B1l;
            uint32_t sdst = sb + (uint32_t)stg * STG_BYTES;
#pragma unroll
            for (int i = 0; i < 12; i++) {
                int unit = i * 256 + tid;
                int arr = unit >> 10;
                int rem = unit & 1023;
                int row = rem >> 3, cg = rem & 7;
                uint32_t dst = sdst + (uint32_t)arr * ARR_BYTES + (uint32_t)(row * PAD + cg * 8) * 2;
                if (arr == 0) {
                    int m = m0 + row;
                    uint32_t sz = (m < M) ? 16u : 0u;
                    int mc = (m < M) ? m : 0;
                    cpa16(dst, arr0 + (size_t)mc * K + kk + cg * 8, sz);
                } else {
                    const __half* base = (arr == 1) ? arr1 : arr2;
                    cpa16(dst, base + (size_t)(n0 + row) * K + kk + cg * 8, 16u);
                }
            }
        };

        issue(0, 0);
        cp_commit();

        for (int c = 0; c < NC; c++) {
            cp_wait<0>();        // chunk c's loads arrived
            __syncthreads();     // all warps consumed chunk c-1 -> its stage is free
            if (c + 1 < NC) { issue(c + 1, (c + 1) & 1); cp_commit(); }

            uint32_t sst = sb + (uint32_t)(c & 1) * STG_BYTES;
            uint32_t aA = sst + a_lane;
            uint32_t bH = sst + ARR_BYTES + b_lane, bL = sst + 2 * ARR_BYTES + b_lane;

#pragma unroll
            for (int ks = 0; ks < CHK / 16; ks++) {
                uint32_t bh[4][2], bl[4][2];
#pragma unroll
                for (int np = 0; np < 2; np++) {
                    uint32_t off = (uint32_t)((warpN * 32 + np * 16) * PAD + ks * 16) * 2;
                    uint32_t r4[4];
                    ldm_x4(r4, bH + off);
                    bh[np * 2][0] = r4[0]; bh[np * 2][1] = r4[1];
                    bh[np * 2 + 1][0] = r4[2]; bh[np * 2 + 1][1] = r4[3];
                    ldm_x4(r4, bL + off);
                    bl[np * 2][0] = r4[0]; bl[np * 2][1] = r4[1];
                    bl[np * 2 + 1][0] = r4[2]; bl[np * 2 + 1][1] = r4[3];
                }
#pragma unroll
                for (int mt = 0; mt < 4; mt++) {
                    uint32_t av[4];
                    uint32_t off = (uint32_t)((warpM * 64 + mt * 16) * PAD + ks * 16) * 2;
                    ldm_x4(av, aA + off);
#pragma unroll
                    for (int nt = 0; nt < 4; nt++) {
                        mma_f16(acc[mt][nt], av, bh[nt]);
                        mma_f16(acc[mt][nt], av, bl[nt]);
                    }
                }
            }
        }
        // NOTE: no sync needed before next tile's issue(0,0): stage 0 was last
        // consumed at c=NC-2, and every warp passed the barrier at c=NC-1.

        // epilogue: bias + relu -> packed fp16 stores
#pragma unroll
        for (int mt = 0; mt < 4; mt++) {
#pragma unroll
            for (int nt = 0; nt < 4; nt++) {
                int n = n0 + warpN * 32 + nt * 8 + (lane & 3) * 2;
                float b0 = __ldg(&bias[n]), b1v = __ldg(&bias[n + 1]);
#pragma unroll
                for (int h = 0; h < 2; h++) {
                    int m = m0 + warpM * 64 + mt * 16 + (lane >> 2) + h * 8;
                    if (m < M) {
                        size_t o = (size_t)m * Nc + n;
                        float v0 = fmaxf(acc[mt][nt][h * 2 + 0] + b0, 0.f);
                        float v1 = fmaxf(acc[mt][nt][h * 2 + 1] + b1v, 0.f);
                        *reinterpret_cast<__half2*>(&C16[o]) = __floats2half2_rn(v0, v1);
                    }
                }
            }
        }
    }
}

// ================= pooling (bounds folded in) + MLP head =================
__global__ void k_pool(const int* __restrict__ batch) {
    __shared__ int bounds[2];
    int g = blockIdx.x >> 2;
    int f = ((blockIdx.x & 3) << 7) + threadIdx.x;
    if (threadIdx.x < 2) {
        int target = g + threadIdx.x;
        int lo = 0, hi = NN;
        while (lo < hi) {
            int mid = (lo + hi) >> 1;
            if (batch[mid] < target) lo = mid + 1; else hi = mid;
        }
        bounds[threadIdx.x] = lo;
    }
    __syncthreads();
    int s0 = bounds[0], s1 = bounds[1];
    float acc = 0.f;
    for (int n = s0; n < s1; n++) acc += __half2float(g_h216[(size_t)n * F1 + f]);
    g_gv[g * F1 + f] = acc / fmaxf((float)(s1 - s0), 1.0f);
}
__global__ void k_mlp(const float* __restrict__ Wl1, const float* __restrict__ bl1,
                      const float* __restrict__ Wl2, const float* __restrict__ bl2,
                      const float* __restrict__ Wl3, const float* __restrict__ bl3,
                      float* __restrict__ out) {
    int g = blockIdx.x, t = threadIdx.x;
    __shared__ float gv[F1], t1[64], t2[16];
    for (int i = t; i < F1; i += 64) gv[i] = g_gv[g * F1 + i];
    __syncthreads();
    float a = bl1[t];
    for (int k = 0; k < F1; k++) a += gv[k] * Wl1[k * 64 + t];
    t1[t] = fmaxf(a, 0.f);
    __syncthreads();
    if (t < 16) {
        float a2 = bl2[t];
        for (int k = 0; k < 64; k++) a2 += t1[k] * Wl2[k * 16 + t];
        t2[t] = fmaxf(a2, 0.f);
    }
    __syncthreads();
    if (t == 0) {
        float a3 = bl3[0];
        for (int k = 0; k < 16; k++) a3 += t2[k] * Wl3[k];
        out[g] = a3;
    }
}

// ================= launch =================
extern "C" void kernel_launch(void* const* d_in, const int* in_sizes, int n_in,
                              void* d_out, int out_size) {
    const float* x       = (const float*)d_in[0];
    const int*   ei      = (const int*)d_in[1];
    const float* ea      = (const float*)d_in[2];
    const int*   batch   = (const int*)d_in[3];
    const float* W1_rel  = (const float*)d_in[4];
    const float* b1      = (const float*)d_in[5];
    const float* W1_root = (const float*)d_in[6];
    const float* W2_rel  = (const float*)d_in[7];
    const float* b2      = (const float*)d_in[8];
    const float* W2_root = (const float*)d_in[9];
    const float* Wl1     = (const float*)d_in[10];
    const float* bl1     = (const float*)d_in[11];
    const float* Wl2     = (const float*)d_in[12];
    const float* bl2     = (const float*)d_in[13];
    const float* Wl3     = (const float*)d_in[14];
    const float* bl3     = (const float*)d_in[15];
    float* out = (float*)d_out;

    static cudaStream_t s2 = nullptr;
    static cudaEvent_t evFork = nullptr, evJoin = nullptr;
    if (!s2) {
        cudaStreamCreateWithFlags(&s2, cudaStreamNonBlocking);
        cudaEventCreateWithFlags(&evFork, cudaEventDisableTiming);
        cudaEventCreateWithFlags(&evJoin, cudaEventDisableTiming);
        cudaFuncSetAttribute(k_gemm_tc, cudaFuncAttributeMaxDynamicSharedMemorySize, SMEM_BYTES);
    }

#define SYM(T, p, s) T* p; cudaGetSymbolAddress((void**)&p, s)
    SYM(__half, x16, g_x16);  SYM(__half, a1, g_a1);
    SYM(__half, h116, g_h116);
    SYM(__half, a2, g_a2);    SYM(__half, h216, g_h216);
    SYM(__half, w1rh, g_w1rh); SYM(__half, w1rl, g_w1rl);
    SYM(__half, w1th, g_w1th); SYM(__half, w1tl, g_w1tl);
    SYM(__half, w2rh, g_w2rh); SYM(__half, w2rl, g_w2rl);
    SYM(__half, w2th, g_w2th); SYM(__half, w2tl, g_w2tl);
#undef SYM

    // fork: prep (weights + x16) on side stream, parallel with CSR chain
    cudaEventRecord(evFork, 0);
    cudaStreamWaitEvent(s2, evFork, 0);
    k_prepwx<<<(PREP_TOT + 255) / 256, 256, 0, s2>>>(W1_rel, W1_root, W2_rel, W2_root, x);
    cudaEventRecord(evJoin, s2);

    // CSR chain on main stream
    k_zero<<<(SCAN_N + 255) / 256, 256>>>();
    k_hist<<<(NE + 255) / 256, 256>>>(ei);
    k_scan<<<1, 1024>>>();
    k_scatter<<<(NE + 255) / 256, 256>>>(ei, ea);

    // join: agg128 needs x16 (prep) + CSR
    cudaStreamWaitEvent(0, evJoin, 0);

    // layer 1: h1(fp16) = relu(agg1@W1_rel + x@W1_root + b1)
    k_agg128<<<(NN + 3) / 4, 128>>>();
    k_gemm_tc<<<GEMM_BLOCKS, 256, SMEM_BYTES>>>(a1, w1rh, w1rl, x16, w1th, w1tl,
                                                F0, b1, h116, NN, F1);
    // layer 2: h2(fp16) = relu(agg2@W2_rel + h1@W2_root + b2)
    k_agg512<<<NN, 128>>>();
    k_gemm_tc<<<GEMM_BLOCKS, 256, SMEM_BYTES>>>(a2, w2rh, w2rl, h116, w2th, w2tl,
                                                F1, b2, h216, NN, F1);
    // pool (+bounds) + head
    k_pool<<<NG * 4, 128>>>(batch);
    k_mlp<<<NG, 64>>>(Wl1, bl1, Wl2, bl2, Wl3, bl3, out);
    (void)in_sizes; (void)n_in; (void)out_size;
}

// round 17
// speedup vs baseline: 1.0279x; 1.0279x over previous
#include <cuda_runtime.h>
#include <cuda_fp16.h>
#include <cstdint>

#define NN 25000
#define NE 400000
#define NG 64
#define F0 128
#define F1 512
#define SCAN_N 28672   // 1024 threads * 28 elems — scan coverage; arrays padded to this

// ================= device scratch (no allocs allowed) =================
__device__ __half g_x16[NN * F0];          // x in fp16
__device__ __half g_a1[NN * F0];           // agg1 fp16
__device__ __half g_h116[NN * F1];         // h1 fp16 (GEMM2 A + agg512 src)
__device__ __half g_a2[NN * F1];           // agg2 fp16
__device__ __half g_h216[NN * F1];         // h2 fp16 (pool src)
__device__ __half g_w1rh[F1 * F0], g_w1rl[F1 * F0];  // W1_rel^T  hi/lo
__device__ __half g_w1th[F1 * F0], g_w1tl[F1 * F0];  // W1_root^T hi/lo
__device__ __half g_w2rh[F1 * F1], g_w2rl[F1 * F1];  // W2_rel^T  hi/lo
__device__ __half g_w2th[F1 * F1], g_w2tl[F1 * F1];  // W2_root^T hi/lo
__device__ int   g_deg[SCAN_N];            // zero at entry (static init + scatter re-zero)
__device__ int   g_rowptr[SCAN_N + 1];
__device__ int   g_epos[NE];               // per-edge slot within its dst row
__device__ int   g_srcs[NE];
__device__ float g_wgts[NE];
__device__ float g_gv[NG * F1];

// ================= helpers =================
__device__ __forceinline__ uint32_t smem_u32(const void* p) {
    uint32_t a;
    asm("{ .reg .u64 t; cvta.to.shared.u64 t, %1; cvt.u32.u64 %0, t; }" : "=r"(a) : "l"(p));
    return a;
}
__device__ __forceinline__ void ldm_x4(uint32_t* r, uint32_t addr) {
    asm volatile("ldmatrix.sync.aligned.m8n8.x4.shared.b16 {%0,%1,%2,%3}, [%4];"
                 : "=r"(r[0]), "=r"(r[1]), "=r"(r[2]), "=r"(r[3]) : "r"(addr));
}
__device__ __forceinline__ void mma_f16(float* c, const uint32_t* a, const uint32_t* b) {
    asm volatile("mma.sync.aligned.m16n8k16.row.col.f32.f16.f16.f32 "
                 "{%0,%1,%2,%3}, {%4,%5,%6,%7}, {%8,%9}, {%0,%1,%2,%3};"
                 : "+f"(c[0]), "+f"(c[1]), "+f"(c[2]), "+f"(c[3])
                 : "r"(a[0]), "r"(a[1]), "r"(a[2]), "r"(a[3]), "r"(b[0]), "r"(b[1]));
}
__device__ __forceinline__ void cpa16(uint32_t dst, const __half* src, uint32_t sz) {
    asm volatile("cp.async.cg.shared.global [%0], [%1], 16, %2;"
                 :: "r"(dst), "l"(__cvta_generic_to_global(src)), "r"(sz) : "memory");
}
__device__ __forceinline__ void cp_commit() {
    asm volatile("cp.async.commit_group;" ::: "memory");
}
template <int N>
__device__ __forceinline__ void cp_wait() {
    asm volatile("cp.async.wait_group %0;" :: "n"(N) : "memory");
}
__device__ __forceinline__ void split2h(float v, __half& h, __half& l) {
    h = __float2half_rn(v);
    l = __float2half_rn(v - __half2float(h));
}

// ================= CSR build =================
// hist also records each edge's slot within its destination row
__global__ void k_hist(const int* __restrict__ ei) {
    int e = blockIdx.x * blockDim.x + threadIdx.x;
    if (e < NE) g_epos[e] = atomicAdd(&g_deg[ei[NE + e]], 1);
}
// vectorized single-block scan: 1024 thr x 28 elems (7 x int4), shuffle-based
#define SCH 28
__global__ __launch_bounds__(1024) void k_scan() {
    __shared__ int wsum[32];
    int t = threadIdx.x;
    int base = t * SCH;
    int v[SCH];
    int4* dv = reinterpret_cast<int4*>(v);
#pragma unroll
    for (int i = 0; i < SCH / 4; i++)
        dv[i] = *reinterpret_cast<const int4*>(&g_deg[base + i * 4]);
    int sum = 0;
#pragma unroll
    for (int i = 0; i < SCH; i++) { int x = v[i]; v[i] = sum; sum += x; }
    int lane = t & 31, wid = t >> 5;
    int inc = sum;
#pragma unroll
    for (int off = 1; off < 32; off <<= 1) {
        int y = __shfl_up_sync(0xFFFFFFFFu, inc, off);
        if (lane >= off) inc += y;
    }
    if (lane == 31) wsum[wid] = inc;
    __syncthreads();
    if (wid == 0) {
        int w = wsum[lane];
#pragma unroll
        for (int off = 1; off < 32; off <<= 1) {
            int y = __shfl_up_sync(0xFFFFFFFFu, w, off);
            if (lane >= off) w += y;
        }
        wsum[lane] = w;
    }
    __syncthreads();
    int warp_excl = (wid == 0) ? 0 : wsum[wid - 1];
    int thread_excl = warp_excl + (inc - sum);
#pragma unroll
    for (int i = 0; i < SCH; i++) v[i] += thread_excl;
#pragma unroll
    for (int i = 0; i < SCH / 4; i++)
        *reinterpret_cast<int4*>(&g_rowptr[base + i * 4]) = dv[i];
    if (t == 1023) g_rowptr[SCAN_N] = wsum[31];
}
// atomic-free scatter using hist-recorded slots; re-zeroes g_deg for the next call
__global__ void k_scatter(const int* __restrict__ ei, const float* __restrict__ ea) {
    int e = blockIdx.x * blockDim.x + threadIdx.x;
    if (e < SCAN_N) g_deg[e] = 0;          // scan already consumed g_deg
    if (e >= NE) return;
    int pos = g_rowptr[ei[NE + e]] + g_epos[e];
    g_srcs[pos] = ei[e];
    g_wgts[pos] = ea[e];
}

// ================= prep: weight splits + x->fp16 (side stream) =================
#define W1_ELEMS (F0 * F1)   // 65536
#define W2_ELEMS (F1 * F1)   // 262144
#define PREP_W (2 * W1_ELEMS + 2 * W2_ELEMS)           // 655360
#define PREP_TOT (PREP_W + NN * F0)                    // + 3200000
__global__ void k_prepwx(const float* __restrict__ W1_rel, const float* __restrict__ W1_root,
                         const float* __restrict__ W2_rel, const float* __restrict__ W2_root,
                         const float* __restrict__ x) {
    int i = blockIdx.x * blockDim.x + threadIdx.x;
    if (i < PREP_W) {
        const float* W; __half* th; __half* tl; int K, idx;
        if (i < W1_ELEMS) { W = W1_rel; th = g_w1rh; tl = g_w1rl; K = F0; idx = i; }
        else if (i < 2 * W1_ELEMS) { W = W1_root; th = g_w1th; tl = g_w1tl; K = F0; idx = i - W1_ELEMS; }
        else if (i < 2 * W1_ELEMS + W2_ELEMS) { W = W2_rel; th = g_w2rh; tl = g_w2rl; K = F1; idx = i - 2 * W1_ELEMS; }
        else { W = W2_root; th = g_w2th; tl = g_w2tl; K = F1; idx = i - 2 * W1_ELEMS - W2_ELEMS; }
        int k = idx / F1, n = idx % F1;   // all weights are [K, 512]
        split2h(W[idx], th[n * K + k], tl[n * K + k]);
    } else if (i < PREP_TOT) {
        int n = i - PREP_W;
        g_x16[n] = __float2half_rn(x[n]);
    }
}

// ================= aggregation (gather-side, atomic-free) =================
__global__ void k_agg128() {
    int node = blockIdx.x * 4 + (threadIdx.x >> 5);
    if (node >= NN) return;
    int lane = threadIdx.x & 31;
    int beg = g_rowptr[node], end = g_rowptr[node + 1];
    float acc0 = 0.f, acc1 = 0.f, acc2 = 0.f, acc3 = 0.f;
    for (int p = beg; p < end; p++) {
        int s = g_srcs[p]; float w = g_wgts[p];
        uint2 raw = *reinterpret_cast<const uint2*>(&g_x16[s * F0 + lane * 4]);
        __half2 v01 = *reinterpret_cast<__half2*>(&raw.x);
        __half2 v23 = *reinterpret_cast<__half2*>(&raw.y);
        float2 f01 = __half22float2(v01), f23 = __half22float2(v23);
        acc0 += w * f01.x; acc1 += w * f01.y; acc2 += w * f23.x; acc3 += w * f23.y;
    }
    int o = node * F0 + lane * 4;
    __half2* dst = reinterpret_cast<__half2*>(&g_a1[o]);
    dst[0] = __floats2half2_rn(acc0, acc1);
    dst[1] = __floats2half2_rn(acc2, acc3);
}
__global__ void k_agg512() {
    int node = blockIdx.x, f4 = threadIdx.x;  // 128 threads, 4 halves each
    int beg = g_rowptr[node], end = g_rowptr[node + 1];
    float acc0 = 0.f, acc1 = 0.f, acc2 = 0.f, acc3 = 0.f;
    for (int p = beg; p < end; p++) {
        int s = g_srcs[p]; float w = g_wgts[p];
        uint2 raw = *reinterpret_cast<const uint2*>(&g_h116[(size_t)s * F1 + f4 * 4]);
        __half2 v01 = *reinterpret_cast<__half2*>(&raw.x);
        __half2 v23 = *reinterpret_cast<__half2*>(&raw.y);
        float2 f01 = __half22float2(v01), f23 = __half22float2(v23);
        acc0 += w * f01.x; acc1 += w * f01.y; acc2 += w * f23.x; acc3 += w * f23.y;
    }
    size_t o = (size_t)node * F1 + f4 * 4;
    __half2* dst = reinterpret_cast<__half2*>(&g_a2[o]);
    dst[0] = __floats2half2_rn(acc0, acc1);
    dst[1] = __floats2half2_rn(acc2, acc3);
}

// ================= tensor-core dual GEMM, fp16 A + split-weight B (2 passes) =================
#define CHK 64
#define PAD 72                       // fp16 row pitch (conflict-free ldmatrix)
#define ARR_BYTES (128 * PAD * 2)    // 18432
#define STG_BYTES (3 * ARR_BYTES)    // 55296 (A, Bh, Bl)
#define SMEM_BYTES (2 * STG_BYTES)   // 110592

__global__ __launch_bounds__(256) void k_gemm_tc(
    const __half* __restrict__ A1, const __half* __restrict__ B1h, const __half* __restrict__ B1l,
    const __half* __restrict__ A2, const __half* __restrict__ B2h, const __half* __restrict__ B2l,
    int K, const float* __restrict__ bias,
    __half* __restrict__ C16,
    int M, int Nc) {
    extern __shared__ char smem[];
    uint32_t sb = smem_u32(smem);
    int tid = threadIdx.x;
    int wid = tid >> 5, lane = tid & 31;
    int warpM = wid >> 2, warpN = wid & 3;   // 2 x 4
    int m0 = blockIdx.y * 128, n0 = blockIdx.x * 128;

    float acc[4][4][4];
#pragma unroll
    for (int i = 0; i < 4; i++)
#pragma unroll
        for (int j = 0; j < 4; j++)
#pragma unroll
            for (int q = 0; q < 4; q++) acc[i][j][q] = 0.f;

    int ncpp = K / CHK;
    int NC = 2 * ncpp;

    uint32_t a_lane = (uint32_t)((lane & 15) * PAD + (lane >> 4) * 8) * 2;
    uint32_t b_lane = (uint32_t)(((lane & 7) + ((lane >> 4) << 3)) * PAD
                                 + ((lane >> 3) & 1) * 8) * 2;

    auto issue = [&](int c, int stg) {
        int ph = c / ncpp;
        int kk = (c % ncpp) * CHK;
        const __half* arr0 = ph ? A2 : A1;
        const __half* arr1 = ph ? B2h : B1h;
        const __half* arr2 = ph ? B2l : B1l;
        uint32_t sdst = sb + (uint32_t)stg * STG_BYTES;
#pragma unroll
        for (int i = 0; i < 12; i++) {
            int unit = i * 256 + tid;
            int arr = unit >> 10;
            int rem = unit & 1023;
            int row = rem >> 3, cg = rem & 7;
            uint32_t dst = sdst + (uint32_t)arr * ARR_BYTES + (uint32_t)(row * PAD + cg * 8) * 2;
            if (arr == 0) {
                int m = m0 + row;
                uint32_t sz = (m < M) ? 16u : 0u;
                int mc = (m < M) ? m : 0;
                cpa16(dst, arr0 + (size_t)mc * K + kk + cg * 8, sz);
            } else {
                const __half* base = (arr == 1) ? arr1 : arr2;
                cpa16(dst, base + (size_t)(n0 + row) * K + kk + cg * 8, 16u);
            }
        }
    };

    issue(0, 0);
    cp_commit();

    for (int c = 0; c < NC; c++) {
        cp_wait<0>();
        __syncthreads();
        if (c + 1 < NC) { issue(c + 1, (c + 1) & 1); cp_commit(); }

        uint32_t sst = sb + (uint32_t)(c & 1) * STG_BYTES;
        uint32_t aA = sst + a_lane;
        uint32_t bH = sst + ARR_BYTES + b_lane, bL = sst + 2 * ARR_BYTES + b_lane;

#pragma unroll
        for (int ks = 0; ks < CHK / 16; ks++) {
            uint32_t bh[4][2], bl[4][2];
#pragma unroll
            for (int np = 0; np < 2; np++) {
                uint32_t off = (uint32_t)((warpN * 32 + np * 16) * PAD + ks * 16) * 2;
                uint32_t r4[4];
                ldm_x4(r4, bH + off);
                bh[np * 2][0] = r4[0]; bh[np * 2][1] = r4[1];
                bh[np * 2 + 1][0] = r4[2]; bh[np * 2 + 1][1] = r4[3];
                ldm_x4(r4, bL + off);
                bl[np * 2][0] = r4[0]; bl[np * 2][1] = r4[1];
                bl[np * 2 + 1][0] = r4[2]; bl[np * 2 + 1][1] = r4[3];
            }
#pragma unroll
            for (int mt = 0; mt < 4; mt++) {
                uint32_t av[4];
                uint32_t off = (uint32_t)((warpM * 64 + mt * 16) * PAD + ks * 16) * 2;
                ldm_x4(av, aA + off);
#pragma unroll
                for (int nt = 0; nt < 4; nt++) {
                    mma_f16(acc[mt][nt], av, bh[nt]);
                    mma_f16(acc[mt][nt], av, bl[nt]);
                }
            }
        }
    }

#pragma unroll
    for (int mt = 0; mt < 4; mt++) {
#pragma unroll
        for (int nt = 0; nt < 4; nt++) {
            int n = n0 + warpN * 32 + nt * 8 + (lane & 3) * 2;
            float b0 = __ldg(&bias[n]), b1v = __ldg(&bias[n + 1]);
#pragma unroll
            for (int h = 0; h < 2; h++) {
                int m = m0 + warpM * 64 + mt * 16 + (lane >> 2) + h * 8;
                if (m < M) {
                    size_t o = (size_t)m * Nc + n;
                    float v0 = fmaxf(acc[mt][nt][h * 2 + 0] + b0, 0.f);
                    float v1 = fmaxf(acc[mt][nt][h * 2 + 1] + b1v, 0.f);
                    *reinterpret_cast<__half2*>(&C16[o]) = __floats2half2_rn(v0, v1);
                }
            }
        }
    }
}

// ================= pooling (bounds folded in) + MLP head =================
__global__ void k_pool(const int* __restrict__ batch) {
    __shared__ int bounds[2];
    int g = blockIdx.x >> 2;
    int f = ((blockIdx.x & 3) << 7) + threadIdx.x;
    if (threadIdx.x < 2) {
        int target = g + threadIdx.x;
        int lo = 0, hi = NN;
        while (lo < hi) {
            int mid = (lo + hi) >> 1;
            if (batch[mid] < target) lo = mid + 1; else hi = mid;
        }
        bounds[threadIdx.x] = lo;
    }
    __syncthreads();
    int s0 = bounds[0], s1 = bounds[1];
    float acc = 0.f;
    for (int n = s0; n < s1; n++) acc += __half2float(g_h216[(size_t)n * F1 + f]);
    g_gv[g * F1 + f] = acc / fmaxf((float)(s1 - s0), 1.0f);
}
__global__ void k_mlp(const float* __restrict__ Wl1, const float* __restrict__ bl1,
                      const float* __restrict__ Wl2, const float* __restrict__ bl2,
                      const float* __restrict__ Wl3, const float* __restrict__ bl3,
                      float* __restrict__ out) {
    int g = blockIdx.x, t = threadIdx.x;
    __shared__ float gv[F1], t1[64], t2[16];
    for (int i = t; i < F1; i += 64) gv[i] = g_gv[g * F1 + i];
    __syncthreads();
    float a = bl1[t];
    for (int k = 0; k < F1; k++) a += gv[k] * Wl1[k * 64 + t];
    t1[t] = fmaxf(a, 0.f);
    __syncthreads();
    if (t < 16) {
        float a2 = bl2[t];
        for (int k = 0; k < 64; k++) a2 += t1[k] * Wl2[k * 16 + t];
        t2[t] = fmaxf(a2, 0.f);
    }
    __syncthreads();
    if (t == 0) {
        float a3 = bl3[0];
        for (int k = 0; k < 16; k++) a3 += t2[k] * Wl3[k];
        out[g] = a3;
    }
}

// ================= launch =================
extern "C" void kernel_launch(void* const* d_in, const int* in_sizes, int n_in,
                              void* d_out, int out_size) {
    const float* x       = (const float*)d_in[0];
    const int*   ei      = (const int*)d_in[1];
    const float* ea      = (const float*)d_in[2];
    const int*   batch   = (const int*)d_in[3];
    const float* W1_rel  = (const float*)d_in[4];
    const float* b1      = (const float*)d_in[5];
    const float* W1_root = (const float*)d_in[6];
    const float* W2_rel  = (const float*)d_in[7];
    const float* b2      = (const float*)d_in[8];
    const float* W2_root = (const float*)d_in[9];
    const float* Wl1     = (const float*)d_in[10];
    const float* bl1     = (const float*)d_in[11];
    const float* Wl2     = (const float*)d_in[12];
    const float* bl2     = (const float*)d_in[13];
    const float* Wl3     = (const float*)d_in[14];
    const float* bl3     = (const float*)d_in[15];
    float* out = (float*)d_out;

    static cudaStream_t s2 = nullptr;
    static cudaEvent_t evFork = nullptr, evJoin = nullptr;
    if (!s2) {
        cudaStreamCreateWithFlags(&s2, cudaStreamNonBlocking);
        cudaEventCreateWithFlags(&evFork, cudaEventDisableTiming);
        cudaEventCreateWithFlags(&evJoin, cudaEventDisableTiming);
        cudaFuncSetAttribute(k_gemm_tc, cudaFuncAttributeMaxDynamicSharedMemorySize, SMEM_BYTES);
    }

#define SYM(T, p, s) T* p; cudaGetSymbolAddress((void**)&p, s)
    SYM(__half, x16, g_x16);  SYM(__half, a1, g_a1);
    SYM(__half, h116, g_h116);
    SYM(__half, a2, g_a2);    SYM(__half, h216, g_h216);
    SYM(__half, w1rh, g_w1rh); SYM(__half, w1rl, g_w1rl);
    SYM(__half, w1th, g_w1th); SYM(__half, w1tl, g_w1tl);
    SYM(__half, w2rh, g_w2rh); SYM(__half, w2rl, g_w2rl);
    SYM(__half, w2th, g_w2th); SYM(__half, w2tl, g_w2tl);
#undef SYM

    // fork: prep (weights + x16) on side stream, parallel with CSR chain
    cudaEventRecord(evFork, 0);
    cudaStreamWaitEvent(s2, evFork, 0);
    k_prepwx<<<(PREP_TOT + 255) / 256, 256, 0, s2>>>(W1_rel, W1_root, W2_rel, W2_root, x);
    cudaEventRecord(evJoin, s2);

    // CSR chain on main stream (g_deg is zero on entry: static init + scatter re-zero)
    k_hist<<<(NE + 255) / 256, 256>>>(ei);
    k_scan<<<1, 1024>>>();
    k_scatter<<<(NE + 255) / 256, 256>>>(ei, ea);

    // join: agg128 needs x16 (prep) + CSR
    cudaStreamWaitEvent(0, evJoin, 0);

    // layer 1: h1(fp16) = relu(agg1@W1_rel + x@W1_root + b1)
    k_agg128<<<(NN + 3) / 4, 128>>>();
    {
        dim3 grid(F1 / 128, (NN + 127) / 128);
        k_gemm_tc<<<grid, 256, SMEM_BYTES>>>(a1, w1rh, w1rl, x16, w1th, w1tl,
                                             F0, b1, h116, NN, F1);
    }
    // layer 2: h2(fp16) = relu(agg2@W2_rel + h1@W2_root + b2)
    k_agg512<<<NN, 128>>>();
    {
        dim3 grid(F1 / 128, (NN + 127) / 128);
        k_gemm_tc<<<grid, 256, SMEM_BYTES>>>(a2, w2rh, w2rl, h116, w2th, w2tl,
                                             F1, b2, h216, NN, F1);
    }
    // pool (+bounds) + head
    k_pool<<<NG * 4, 128>>>(batch);
    k_mlp<<<NG, 64>>>(Wl1, bl1, Wl2, bl2, Wl3, bl3, out);
    (void)in_sizes; (void)n_in; (void)out_size;
}